// round 16
// baseline (speedup 1.0000x reference)
#include <cuda_runtime.h>
#include <math.h>

#define NIMG 32      // B*G
#define HW   260
#define ES   65      // encoder output spatial
#define DCH  128     // encoder channels
#define S2   162     // correlation channels (81*2)
#define U1   130     // first upsample size
#define HT   258     // texture spatial
#define ED   8
#define ED2  16
#define HWHW (HW*HW)
#define HTHT (HT*HT)

// ---------------- scratch (device globals; no allocation) ----------------
__device__ float g_fnm[NIMG*ES*ES*DCH];     // [n][y][x][c]
__device__ float g_fpm[NIMG*ES*ES*DCH];
__device__ float g_fpb[NIMG*ES*ES*DCH];
__device__ float g_corr[NIMG*ES*ES*S2];     // [n][y][x][s]
__device__ float g_upcorr[NIMG*U1*U1*S2];   // [n][y][x][s]
__device__ float g_t1[NIMG*U1*U1*ED2];      // [n][y][x][oc16]
__device__ float g_upt1[NIMG*HW*HW*ED2];    // [n][y][x][oc16]
__device__ float g_phi[NIMG*HWHW];          // plane
__device__ float g_vort[NIMG*HWHW];         // plane
__device__ float g_velx[NIMG*HTHT];
__device__ float g_vely[NIMG*HTHT];
__device__ float g_wa[NIMG*ED*HTHT];        // warp scratch 1 (f1)
__device__ float g_wb[NIMG*ED*HTHT];        // warp scratch 2 (f2)
__device__ float g_vortk[2][36];
__device__ float g_wt[128*128];             // enc_w transposed: [j][oc]

// ---------------- init: vorticity kernel + enc weight transpose ----------------
__global__ void init_kernel(const float* __restrict__ enc_w) {
    int tid = blockIdx.x * blockDim.x + threadIdx.x;
    if (tid < 36) {
        int ky = tid / 6, kx = tid % 6;
        float yc = (float)ky - 2.5f, xc = (float)kx - 2.5f;
        float r2 = yc*yc + xc*xc;
        float inv = 1.0f / (2.0f * 3.14159265358979323846f * r2);
        g_vortk[0][tid] = -yc * inv;
        g_vortk[1][tid] =  xc * inv;
    }
    for (int i = tid; i < 128*128; i += gridDim.x * blockDim.x) {
        int oc = i >> 7, j = i & 127;
        g_wt[j*128 + oc] = enc_w[i];
    }
}

// ---------------- encoder: stride-4 4x4 conv, mask fused, transposed weights ----------------
__global__ __launch_bounds__(128) void enc_kernel(
        const float* __restrict__ in, const float* __restrict__ m,
        const float* __restrict__ wt, const float* __restrict__ bias,
        float* __restrict__ out)
{
    const int PPB = 16;
    __shared__ float patch[PPB][128];
    int n = blockIdx.y;
    int b = n >> 3, g = n & 7;
    int tid = threadIdx.x;          // = oc in compute phase
    int pix0 = blockIdx.x * PPB;

    int ic = tid >> 4, r = tid & 15, ky = r >> 2, kx = r & 3;
    const float* inb = in + ((long)(b*64 + g*8 + ic))*HWHW;
    const float* mb  = m  + (long)b*HWHW;
    #pragma unroll
    for (int p = 0; p < PPB; p++) {
        int pix = pix0 + p;
        float v = 0.f;
        if (pix < ES*ES) {
            int oy = pix / ES, ox = pix % ES;
            int iy = oy*4 + ky, ix = ox*4 + kx;
            v = inb[iy*HW + ix] * mb[iy*HW + ix];
        }
        patch[p][tid] = v;
    }
    __syncthreads();

    float acc[PPB];
    float bv = bias[tid];
    #pragma unroll
    for (int p = 0; p < PPB; p++) acc[p] = bv;
    #pragma unroll 4
    for (int i = 0; i < 32; i++) {
        // coalesced scalar weight loads: lanes (=oc) consecutive
        float4 wv;
        wv.x = wt[(4*i+0)*128 + tid];
        wv.y = wt[(4*i+1)*128 + tid];
        wv.z = wt[(4*i+2)*128 + tid];
        wv.w = wt[(4*i+3)*128 + tid];
        #pragma unroll
        for (int p = 0; p < PPB; p++) {
            float4 xv = ((const float4*)patch[p])[i];
            acc[p] += xv.x*wv.x + xv.y*wv.y + xv.z*wv.z + xv.w*wv.w;
        }
    }
    #pragma unroll
    for (int p = 0; p < PPB; p++) {
        int pix = pix0 + p;
        if (pix < ES*ES) out[((long)n*ES*ES + pix)*128 + tid] = acc[p];
    }
}

// ---------------- correlation: 8-px tile, a in regs, shared b reads ----------------
// dyn smem: bsm[144][132]  (76,032 B)
__global__ __launch_bounds__(256) void corr_kernel(
        const float* __restrict__ fpm, const float* __restrict__ fpb,
        const float* __restrict__ fnm, float* __restrict__ corr)
{
    extern __shared__ float bsm[];       // [row 144][132]
    int blk = blockIdx.x;                // n*(65*9) + y*9 + xt
    int xt = blk % 9; int t = blk / 9;
    int y = t % ES;   int n = t / ES;
    int x0 = xt * 8;
    int tid = threadIdx.x;

    for (int i = tid; i < 144*32; i += 256) {
        int rc = i >> 5, c4 = i & 31;
        int dyi = rc >> 4, xc = rc & 15;
        int yy = y + dyi - 4, xx = x0 + xc - 4;
        float4 val = make_float4(0.f,0.f,0.f,0.f);
        if (yy >= 0 && yy < ES && xx >= 0 && xx < ES)
            val = ((const float4*)(fnm + ((long)n*ES*ES + yy*ES + xx)*128))[c4];
        *(float4*)(bsm + rc*132 + c4*4) = val;
    }
    __syncthreads();

    int w = tid >> 5;                    // warp = pixel index in tile
    int lane = tid & 31;
    int g = lane >> 2, q = lane & 3;     // 8 groups x 4 lanes
    int x = x0 + w;
    if (x >= ES) return;                 // warp-uniform (after the only sync)

    long apos = ((long)n*ES*ES + y*ES + x)*128;
    const float4* pm4 = (const float4*)(fpm + apos);
    const float4* pb4 = (const float4*)(fpb + apos);
    float4 am[8], ab[8];
    #pragma unroll
    for (int j = 0; j < 8; j++) {
        am[j] = pm4[j*4 + q];
        ab[j] = pb4[j*4 + q];
    }

    long obase = ((long)n*ES*ES + y*ES + x)*(long)S2;
    #pragma unroll
    for (int tb = 0; tb < 11; tb++) {
        int s = tb*8 + g;
        float dm = 0.f, db = 0.f;
        if (s < 81) {
            int dyi = s / 9, dxi = s % 9;
            const float* brow = bsm + (dyi*16 + w + dxi)*132;
            #pragma unroll
            for (int j = 0; j < 8; j++) {
                float4 bv = *(const float4*)(brow + (j*4 + q)*4);
                dm += am[j].x*bv.x + am[j].y*bv.y + am[j].z*bv.z + am[j].w*bv.w;
                db += ab[j].x*bv.x + ab[j].y*bv.y + ab[j].z*bv.z + ab[j].w*bv.w;
            }
        }
        dm += __shfl_xor_sync(0xffffffffu, dm, 1);
        dm += __shfl_xor_sync(0xffffffffu, dm, 2);
        db += __shfl_xor_sync(0xffffffffu, db, 1);
        db += __shfl_xor_sync(0xffffffffu, db, 2);
        if (q == 0 && s < 81) {
            corr[obase + s]      = dm * (1.0f/128.0f);
            corr[obase + 81 + s] = db * (1.0f/128.0f);
        }
    }
}

// ---------------- up2x (align_corners-style lerp, matches reference) ----------------
__global__ void up2x_kernel(const float* __restrict__ in, float* __restrict__ out,
                            int h, int ch, int nimg)
{
    long total = (long)nimg * (2*h) * (2*h) * ch;
    long idx = (long)blockIdx.x * blockDim.x + threadIdx.x;
    if (idx >= total) return;
    int c = (int)(idx % ch); long t = idx / ch;
    int h2 = 2*h;
    int xo = (int)(t % h2); t /= h2; int yo = (int)(t % h2); int n = (int)(t / h2);
    float fy = (float)(yo * (h-1)) / (float)(h2 - 1);
    float fx = (float)(xo * (h-1)) / (float)(h2 - 1);
    int iy0 = (int)floorf(fy), ix0 = (int)floorf(fx);
    float wy = fy - (float)iy0, wx = fx - (float)ix0;
    int iy1 = min(iy0+1, h-1), ix1 = min(ix0+1, h-1);
    const float* base = in + (long)n*h*h*ch;
    float v00 = base[(iy0*h + ix0)*ch + c];
    float v10 = base[(iy1*h + ix0)*ch + c];
    float v01 = base[(iy0*h + ix1)*ch + c];
    float v11 = base[(iy1*h + ix1)*ch + c];
    out[idx] = (v00*(1.f-wy) + v10*wy)*(1.f-wx) + (v01*(1.f-wy) + v11*wy)*wx;
}

// ---------------- conv1 fused (phi+vor): 3x3, 162 -> 16, row-aligned, 6-wide window ----------------
// dyn smem: ws[9][16][162] (93,312 B). 2 CTAs/SM pinned via launch_bounds.
__global__ __launch_bounds__(256, 2) void conv1_kernel(
        const float* __restrict__ in,
        const float* __restrict__ pw, const float* __restrict__ pg, const float* __restrict__ pb,
        const float* __restrict__ vw, const float* __restrict__ vg, const float* __restrict__ vb,
        float* __restrict__ out)
{
    extern __shared__ float ws[];        // [kk][oc16][ic]
    __shared__ float scale[ED2], bsh[ED2];
    int tid = threadIdx.x;
    for (int i = tid; i < 9*16*S2; i += 256) {
        int ic = i % S2; int t = i / S2; int oc = t & 15; int kk = t >> 4;
        ws[i] = (oc < 8) ? pw[(oc*S2 + ic)*9 + kk] : vw[((oc-8)*S2 + ic)*9 + kk];
    }
    if (tid < 8) {
        scale[tid]   = pg[tid] * rsqrtf(1.0f + 1e-5f);  bsh[tid]   = pb[tid];
        scale[tid+8] = vg[tid] * rsqrtf(1.0f + 1e-5f);  bsh[tid+8] = vb[tid];
    }
    __syncthreads();

    int lane = tid & 31;
    int wid = blockIdx.x*8 + (tid >> 5);   // global warp id
    int row = wid / 33;                    // n*U1 + y  (33 groups of 4 px per row)
    int xt  = wid % 33;
    int n = row / U1, y = row % U1;
    int x0 = xt * 4;
    long nbase = (long)n * (U1*U1);

    float acc[4][ED2];
    #pragma unroll
    for (int p = 0; p < 4; p++)
        #pragma unroll
        for (int o = 0; o < ED2; o++) acc[p][o] = 0.f;

    #pragma unroll
    for (int ky = 0; ky < 3; ky++) {
        int iy = y + ky - 1;
        bool rowok = (iy >= 0 && iy < U1);
        const float* rbase = in + (nbase + (long)iy*U1)*(long)S2;
        #pragma unroll
        for (int jp = 0; jp < 3; jp++) {
            int ic2 = jp*32 + lane;
            bool act = ic2 < 81;           // 81 float2 per channel row
            int ic2c = act ? ic2 : 0;
            float2 vv[6];
            #pragma unroll
            for (int j = 0; j < 6; j++) {
                int ix = x0 - 1 + j;
                bool ok = rowok && act && ix >= 0 && ix < U1;
                vv[j] = ok ? ((const float2*)(rbase + (long)ix*S2))[ic2c]
                           : make_float2(0.f, 0.f);
            }
            #pragma unroll
            for (int kx = 0; kx < 3; kx++) {
                const float* wpt = ws + (ky*3 + kx)*(16*S2);
                #pragma unroll
                for (int half = 0; half < 2; half++) {
                    float2 wv[8];
                    #pragma unroll
                    for (int o = 0; o < 8; o++)
                        wv[o] = ((const float2*)(wpt + (half*8 + o)*S2))[ic2c];
                    #pragma unroll
                    for (int p = 0; p < 4; p++)
                        #pragma unroll
                        for (int o = 0; o < 8; o++)
                            acc[p][half*8 + o] += vv[kx+p].x*wv[o].x + vv[kx+p].y*wv[o].y;
                }
            }
        }
    }
    // butterfly reduce across lanes (all lanes end with full sums)
    #pragma unroll
    for (int off = 16; off > 0; off >>= 1)
        #pragma unroll
        for (int p = 0; p < 4; p++)
            #pragma unroll
            for (int o = 0; o < ED2; o++)
                acc[p][o] += __shfl_xor_sync(0xffffffffu, acc[p][o], off);

    #pragma unroll
    for (int p = 0; p < 4; p++) {
        if (lane == p && x0 + p < U1) {
            float* op = out + (nbase + (long)y*U1 + x0 + p)*ED2;
            #pragma unroll
            for (int o = 0; o < ED2; o++)
                op[o] = fmaxf(acc[p][o]*scale[o] + bsh[o], 0.f);
        }
    }
}

// ---------------- conv2 fused: 3x3, (8->8)x2 branches, + bn/relu/1x1/scale ----------------
__global__ __launch_bounds__(256) void conv2_kernel(
        const float* __restrict__ in,
        const float* __restrict__ pw, const float* __restrict__ pg, const float* __restrict__ pb,
        const float* __restrict__ pow_, const float* __restrict__ pob, const float* __restrict__ pwt,
        const float* __restrict__ vw, const float* __restrict__ vg, const float* __restrict__ vb,
        const float* __restrict__ vow_, const float* __restrict__ vob, const float* __restrict__ vwt,
        float* __restrict__ phi, float* __restrict__ vort)
{
    __shared__ float ws[9*16*8];       // [kk][oc16][ic8]
    __shared__ float scale[ED2], bsh[ED2], owsh[ED2];
    int tid = threadIdx.x;
    for (int i = tid; i < 1152; i += 256) {
        int ic = i & 7, oc = (i >> 3) & 15, kk = i >> 7;
        ws[i] = (oc < 8) ? pw[(oc*8 + ic)*9 + kk] : vw[((oc-8)*8 + ic)*9 + kk];
    }
    if (tid < 8) {
        scale[tid]   = pg[tid] * rsqrtf(1.0f + 1e-5f);  bsh[tid]   = pb[tid];  owsh[tid]   = pow_[tid];
        scale[tid+8] = vg[tid] * rsqrtf(1.0f + 1e-5f);  bsh[tid+8] = vb[tid];  owsh[tid+8] = vow_[tid];
    }
    __syncthreads();

    int pix = blockIdx.x * 256 + tid;
    int x = pix % HW; int t = pix / HW; int y = t % HW; int n = t / HW;

    float acc[ED2];
    #pragma unroll
    for (int oc = 0; oc < ED2; oc++) acc[oc] = 0.f;

    #pragma unroll
    for (int ky = 0; ky < 3; ky++) {
        int iy = y + ky - 1; if (iy < 0 || iy >= HW) continue;
        #pragma unroll
        for (int kx = 0; kx < 3; kx++) {
            int ix = x + kx - 1; if (ix < 0 || ix >= HW) continue;
            const float4* ip4 = (const float4*)(in + ((long)n*HWHW + iy*HW + ix)*ED2);
            float4 s0 = ip4[0], s1 = ip4[1], s2 = ip4[2], s3 = ip4[3];
            const float* wp = ws + (ky*3 + kx)*128;
            #pragma unroll
            for (int oc = 0; oc < 8; oc++) {
                const float4* wq = (const float4*)(wp + oc*8);
                float4 w0 = wq[0], w1 = wq[1];
                acc[oc] += s0.x*w0.x + s0.y*w0.y + s0.z*w0.z + s0.w*w0.w
                         + s1.x*w1.x + s1.y*w1.y + s1.z*w1.z + s1.w*w1.w;
            }
            #pragma unroll
            for (int oc = 0; oc < 8; oc++) {
                const float4* wq = (const float4*)(wp + 64 + oc*8);
                float4 w0 = wq[0], w1 = wq[1];
                acc[8+oc] += s2.x*w0.x + s2.y*w0.y + s2.z*w0.z + s2.w*w0.w
                           + s3.x*w1.x + s3.y*w1.y + s3.z*w1.z + s3.w*w1.w;
            }
        }
    }
    float rp = 0.f, rv = 0.f;
    #pragma unroll
    for (int oc = 0; oc < 8; oc++)
        rp += fmaxf(acc[oc]*scale[oc] + bsh[oc], 0.f) * owsh[oc];
    #pragma unroll
    for (int oc = 0; oc < 8; oc++)
        rv += fmaxf(acc[8+oc]*scale[8+oc] + bsh[8+oc], 0.f) * owsh[8+oc];
    phi[pix]  = (rp + pob[0]) * pwt[0];
    vort[pix] = (rv + vob[0]) * vwt[0] * 260.0f;
}

// ---------------- velocity: fused helmholtz decode ----------------
__global__ void vel_kernel(const float* __restrict__ phi, const float* __restrict__ vort,
                           float* __restrict__ velx, float* __restrict__ vely)
{
    __shared__ float ku[36], kv[36];
    if (threadIdx.x < 36) { ku[threadIdx.x] = g_vortk[0][threadIdx.x]; kv[threadIdx.x] = g_vortk[1][threadIdx.x]; }
    __syncthreads();
    int idx = blockIdx.x * blockDim.x + threadIdx.x;
    if (idx >= NIMG*HTHT) return;
    int xo = idx % HT; int t = idx / HT; int yo = t % HT; int n = t / HT;
    const float* ph = phi  + (long)n*HWHW;
    const float* vo = vort + (long)n*HWHW;

    float vx = 0.5f*(ph[(yo+1)*HW + xo+2] - ph[(yo+1)*HW + xo]);
    float vy = 0.5f*(ph[(yo+2)*HW + xo+1] - ph[yo*HW + xo+1]);

    float p[7][7];
    #pragma unroll
    for (int r = 0; r < 7; r++) {
        int a = yo - 3 + r;
        #pragma unroll
        for (int c = 0; c < 7; c++) {
            int bcol = xo - 3 + c;
            p[r][c] = (a >= 0 && a <= 258 && bcol >= 0 && bcol <= 258) ? vo[a*HW + bcol] : 0.f;
        }
    }
    float su = 0.f, sv = 0.f;
    #pragma unroll
    for (int ky = 0; ky < 6; ky++)
        #pragma unroll
        for (int kx = 0; kx < 6; kx++) {
            su += ku[ky*6+kx] * (p[ky+1][kx+1] + p[ky+1][kx]);
            sv += kv[ky*6+kx] * (p[ky+1][kx+1] + p[ky][kx+1]);
        }
    velx[idx] = vx + 0.5f*su;
    vely[idx] = vy + 0.5f*sv;
}

// ---------------- bilinear warp (modes: 0=plain, 1=BFECC combine) ----------------
__global__ void warp_kernel(const float* __restrict__ src, const float* __restrict__ base,
                            const float* __restrict__ velx, const float* __restrict__ vely,
                            float sign, int mode, float* __restrict__ dst)
{
    int idx = blockIdx.x * blockDim.x + threadIdx.x;
    if (idx >= NIMG*HTHT) return;
    int x = idx % HT; int t = idx / HT; int y = t % HT; int n = t / HT;
    float px = (float)x - sign * velx[idx];
    float py = (float)y - sign * vely[idx];
    px = fminf(fmaxf(px, 0.f), (float)(HT-1));
    py = fminf(fmaxf(py, 0.f), (float)(HT-1));
    float fx = floorf(px), fy = floorf(py);
    float wx = px - fx, wy = py - fy;
    int x0 = (int)fx, y0 = (int)fy;
    int x1 = min(x0+1, HT-1), y1 = min(y0+1, HT-1);
    int o00 = y0*HT + x0, o01 = y0*HT + x1, o10 = y1*HT + x0, o11 = y1*HT + x1;
    int sp = y*HT + x;
    #pragma unroll
    for (int c = 0; c < ED; c++) {
        long pbase = (long)(n*ED + c) * HTHT;
        const float* pl = src + pbase;
        float v = (pl[o00]*(1.f-wx) + pl[o01]*wx)*(1.f-wy)
                + (pl[o10]*(1.f-wx) + pl[o11]*wx)*wy;
        float r = (mode == 1) ? (1.5f * base[pbase + sp] - 0.5f * v) : v;
        dst[pbase + sp] = r;
    }
}

// ---------------- per-pixel LayerNorm + MLP(64->64 gelu ->64) + residual ----------------
// 16 px/block, 4 px/thread-group
__global__ __launch_bounds__(256) void mlp_kernel(float* __restrict__ out,
                           const float* __restrict__ lng, const float* __restrict__ lnb,
                           const float* __restrict__ w1, const float* __restrict__ b1,
                           const float* __restrict__ w2, const float* __restrict__ b2)
{
    __shared__ float w1s[64*65], w2s[64*65];   // transposed, stride-65 (bank-safe)
    __shared__ float xn[16][64];
    __shared__ float hh[16][64];
    int tid = threadIdx.x;
    for (int i = tid; i < 4096; i += 256) {
        int r = i >> 6, cc = i & 63;           // r = out idx, cc = in idx
        w1s[cc*65 + r] = w1[i];
        w2s[cc*65 + r] = w2[i];
    }
    int c  = tid & 63;
    int g0 = (tid >> 6) * 4;                   // 4 pixels per thread, 16 per block
    float lg = lng[c], lb = lnb[c], b1v = b1[c], b2v = b2[c];

    int pix0 = blockIdx.x*16 + g0;             // grid exact: 4*HTHT/16

    float v[4]; float* pp[4];
    #pragma unroll
    for (int k = 0; k < 4; k++) {
        int pix = pix0 + k;
        int bi = pix / HTHT, sp = pix % HTHT;
        pp[k] = out + ((long)(bi*64 + c))*HTHT + sp;
        v[k] = *pp[k];
    }
    __syncthreads();
    #pragma unroll
    for (int k = 0; k < 4; k++) xn[g0+k][c] = v[k];
    __syncthreads();
    float xv[4];
    #pragma unroll
    for (int k = 0; k < 4; k++) {
        float mu = 0.f, m2 = 0.f;
        #pragma unroll 8
        for (int i = 0; i < 64; i++) { float tv = xn[g0+k][i]; mu += tv; m2 += tv*tv; }
        mu *= (1.0f/64.0f); m2 *= (1.0f/64.0f);
        float rs = rsqrtf(m2 - mu*mu + 1e-5f);
        xv[k] = (v[k] - mu)*rs*lg + lb;
    }
    __syncthreads();
    #pragma unroll
    for (int k = 0; k < 4; k++) xn[g0+k][c] = xv[k];
    __syncthreads();
    float h[4];
    #pragma unroll
    for (int k = 0; k < 4; k++) h[k] = b1v;
    #pragma unroll 8
    for (int i = 0; i < 64; i++) {
        float wv = w1s[i*65 + c];
        #pragma unroll
        for (int k = 0; k < 4; k++) h[k] += xn[g0+k][i]*wv;
    }
    #pragma unroll
    for (int k = 0; k < 4; k++) {
        h[k] = 0.5f*h[k]*(1.0f + erff(h[k]*0.70710678118654752f));
        hh[g0+k][c] = h[k];
    }
    __syncthreads();
    float yv[4];
    #pragma unroll
    for (int k = 0; k < 4; k++) yv[k] = b2v;
    #pragma unroll 8
    for (int j = 0; j < 64; j++) {
        float wv = w2s[j*65 + c];
        #pragma unroll
        for (int k = 0; k < 4; k++) yv[k] += hh[g0+k][j]*wv;
    }
    #pragma unroll
    for (int k = 0; k < 4; k++) *pp[k] = v[k] + yv[k];
}

// ---------------- launch ----------------
extern "C" void kernel_launch(void* const* d_in, const int* in_sizes, int n_in,
                              void* d_out, int out_size)
{
    const float* prev     = (const float*)d_in[0];
    const float* nxt      = (const float*)d_in[1];
    const float* texture  = (const float*)d_in[2];
    const float* mask     = (const float*)d_in[3];
    const float* boundary = (const float*)d_in[4];
    const float* enc_w    = (const float*)d_in[5];
    const float* enc_b    = (const float*)d_in[6];
    const float* phi_w1   = (const float*)d_in[7];
    const float* phi_g1   = (const float*)d_in[8];
    const float* phi_b1   = (const float*)d_in[9];
    const float* phi_w2   = (const float*)d_in[10];
    const float* phi_g2   = (const float*)d_in[11];
    const float* phi_b2   = (const float*)d_in[12];
    const float* phi_ow   = (const float*)d_in[13];
    const float* phi_ob   = (const float*)d_in[14];
    const float* vor_w1   = (const float*)d_in[15];
    const float* vor_g1   = (const float*)d_in[16];
    const float* vor_b1   = (const float*)d_in[17];
    const float* vor_w2   = (const float*)d_in[18];
    const float* vor_g2   = (const float*)d_in[19];
    const float* vor_b2   = (const float*)d_in[20];
    const float* vor_ow   = (const float*)d_in[21];
    const float* vor_ob   = (const float*)d_in[22];
    const float* phi_wt   = (const float*)d_in[23];
    const float* vor_wt   = (const float*)d_in[24];
    const float* ln_g     = (const float*)d_in[25];
    const float* ln_b     = (const float*)d_in[26];
    const float* fc1_w    = (const float*)d_in[27];
    const float* fc1_b    = (const float*)d_in[28];
    const float* fc2_w    = (const float*)d_in[29];
    const float* fc2_b    = (const float*)d_in[30];
    float* outp = (float*)d_out;

    float *fnm, *fpm, *fpb, *corr, *upcorr, *t1, *upt1, *phi, *vort, *velx, *vely, *wa, *wb, *wt;
    cudaGetSymbolAddress((void**)&fnm,    g_fnm);
    cudaGetSymbolAddress((void**)&fpm,    g_fpm);
    cudaGetSymbolAddress((void**)&fpb,    g_fpb);
    cudaGetSymbolAddress((void**)&corr,   g_corr);
    cudaGetSymbolAddress((void**)&upcorr, g_upcorr);
    cudaGetSymbolAddress((void**)&t1,     g_t1);
    cudaGetSymbolAddress((void**)&upt1,   g_upt1);
    cudaGetSymbolAddress((void**)&phi,    g_phi);
    cudaGetSymbolAddress((void**)&vort,   g_vort);
    cudaGetSymbolAddress((void**)&velx,   g_velx);
    cudaGetSymbolAddress((void**)&vely,   g_vely);
    cudaGetSymbolAddress((void**)&wa,     g_wa);
    cudaGetSymbolAddress((void**)&wb,     g_wb);
    cudaGetSymbolAddress((void**)&wt,     g_wt);

    const int corr_smem = 144*132*4;     // 76,032 B
    const int c1_smem   = 9*16*S2*4;     // 93,312 B
    cudaFuncSetAttribute(corr_kernel, cudaFuncAttributeMaxDynamicSharedMemorySize, corr_smem);
    cudaFuncSetAttribute(conv1_kernel, cudaFuncAttributeMaxDynamicSharedMemorySize, c1_smem);

    init_kernel<<<32, 512>>>(enc_w);

    dim3 egrid((ES*ES + 15)/16, NIMG);
    enc_kernel<<<egrid, 128>>>(nxt,  mask,     wt, enc_b, fnm);
    enc_kernel<<<egrid, 128>>>(prev, mask,     wt, enc_b, fpm);
    enc_kernel<<<egrid, 128>>>(prev, boundary, wt, enc_b, fpb);

    corr_kernel<<<NIMG*ES*9, 256, corr_smem>>>(fpm, fpb, fnm, corr);

    {
        long total = (long)NIMG*U1*U1*S2;
        up2x_kernel<<<(unsigned)((total + 255)/256), 256>>>(corr, upcorr, ES, S2, NIMG);
    }

    // decoder: fused conv1 (162->16, one pass), one 16-ch up2x, fused conv2
    int c1blocks = (NIMG*U1*33) / 8;     // row-aligned: 33 groups of 4 px per row
    conv1_kernel<<<c1blocks, 256, c1_smem>>>(upcorr,
        phi_w1, phi_g1, phi_b1, vor_w1, vor_g1, vor_b1, t1);
    {
        long total = (long)NIMG*HWHW*ED2;
        up2x_kernel<<<(unsigned)((total + 255)/256), 256>>>(t1, upt1, U1, ED2, NIMG);
    }
    conv2_kernel<<<(NIMG*HWHW)/256, 256>>>(upt1,
        phi_w2, phi_g2, phi_b2, phi_ow, phi_ob, phi_wt,
        vor_w2, vor_g2, vor_b2, vor_ow, vor_ob, vor_wt,
        phi, vort);

    int vblocks = (NIMG*HTHT + 255)/256;
    vel_kernel<<<vblocks, 256>>>(phi, vort, velx, vely);

    // BFECC: f1 = warp(tex,+1); f2 = 1.5*tex - 0.5*warp(f1,-1); pred = warp(f2,+1)
    warp_kernel<<<vblocks, 256>>>(texture, nullptr,  velx, vely,  1.0f, 0, wa);
    warp_kernel<<<vblocks, 256>>>(wa,      texture,  velx, vely, -1.0f, 1, wb);
    warp_kernel<<<vblocks, 256>>>(wb,      nullptr,  velx, vely,  1.0f, 0, outp);

    // 16 px per block, 4 px per thread: grid = 4*HTHT/16 (exact: 266256/16 = 16641)
    mlp_kernel<<<(4*HTHT)/16, 256>>>(outp, ln_g, ln_b, fc1_w, fc1_b, fc2_w, fc2_b);
}

// round 17
// speedup vs baseline: 1.0703x; 1.0703x over previous
#include <cuda_runtime.h>
#include <math.h>

#define NIMG 32      // B*G
#define HW   260
#define ES   65      // encoder output spatial
#define DCH  128     // encoder channels
#define S2   162     // correlation channels (81*2)
#define U1   130     // first upsample size
#define HT   258     // texture spatial
#define ED   8
#define ED2  16
#define HWHW (HW*HW)
#define HTHT (HT*HT)

// ---------------- scratch (device globals; no allocation) ----------------
__device__ float g_fnm[NIMG*ES*ES*DCH];     // [n][y][x][c]
__device__ float g_fpm[NIMG*ES*ES*DCH];
__device__ float g_fpb[NIMG*ES*ES*DCH];
__device__ float g_corr[NIMG*ES*ES*S2];     // [n][y][x][s]
__device__ float g_upcorr[NIMG*U1*U1*S2];   // [n][y][x][s]
__device__ float g_t1[NIMG*U1*U1*ED2];      // [n][y][x][oc16]
__device__ float g_upt1[NIMG*HW*HW*ED2];    // [n][y][x][oc16]
__device__ float g_phi[NIMG*HWHW];          // plane
__device__ float g_vort[NIMG*HWHW];         // plane
__device__ float g_velx[NIMG*HTHT];
__device__ float g_vely[NIMG*HTHT];
__device__ float g_wa[NIMG*ED*HTHT];        // warp scratch 1 (f1)
__device__ float g_wb[NIMG*ED*HTHT];        // warp scratch 2 (f2)
__device__ float g_vortk[2][36];
__device__ float g_wt[128*128];             // enc_w transposed: [j][oc]

// ---------------- init: vorticity kernel + enc weight transpose ----------------
__global__ void init_kernel(const float* __restrict__ enc_w) {
    int tid = blockIdx.x * blockDim.x + threadIdx.x;
    if (tid < 36) {
        int ky = tid / 6, kx = tid % 6;
        float yc = (float)ky - 2.5f, xc = (float)kx - 2.5f;
        float r2 = yc*yc + xc*xc;
        float inv = 1.0f / (2.0f * 3.14159265358979323846f * r2);
        g_vortk[0][tid] = -yc * inv;
        g_vortk[1][tid] =  xc * inv;
    }
    for (int i = tid; i < 128*128; i += gridDim.x * blockDim.x) {
        int oc = i >> 7, j = i & 127;
        g_wt[j*128 + oc] = enc_w[i];
    }
}

// ---------------- encoder: stride-4 4x4 conv, mask fused, transposed weights, 32 px/block ----------------
__global__ __launch_bounds__(128) void enc_kernel(
        const float* __restrict__ in, const float* __restrict__ m,
        const float* __restrict__ wt, const float* __restrict__ bias,
        float* __restrict__ out)
{
    const int PPB = 32;
    __shared__ float patch[PPB][128];
    int n = blockIdx.y;
    int b = n >> 3, g = n & 7;
    int tid = threadIdx.x;          // = oc in compute phase
    int pix0 = blockIdx.x * PPB;

    int ic = tid >> 4, r = tid & 15, ky = r >> 2, kx = r & 3;
    const float* inb = in + ((long)(b*64 + g*8 + ic))*HWHW;
    const float* mb  = m  + (long)b*HWHW;
    #pragma unroll
    for (int p = 0; p < PPB; p++) {
        int pix = pix0 + p;
        float v = 0.f;
        if (pix < ES*ES) {
            int oy = pix / ES, ox = pix % ES;
            int iy = oy*4 + ky, ix = ox*4 + kx;
            v = inb[iy*HW + ix] * mb[iy*HW + ix];
        }
        patch[p][tid] = v;
    }
    __syncthreads();

    float acc[PPB];
    float bv = bias[tid];
    #pragma unroll
    for (int p = 0; p < PPB; p++) acc[p] = bv;
    #pragma unroll 4
    for (int i = 0; i < 32; i++) {
        // coalesced scalar weight loads: lanes (=oc) consecutive
        float4 wv;
        wv.x = wt[(4*i+0)*128 + tid];
        wv.y = wt[(4*i+1)*128 + tid];
        wv.z = wt[(4*i+2)*128 + tid];
        wv.w = wt[(4*i+3)*128 + tid];
        #pragma unroll
        for (int p = 0; p < PPB; p++) {
            float4 xv = ((const float4*)patch[p])[i];
            acc[p] += xv.x*wv.x + xv.y*wv.y + xv.z*wv.z + xv.w*wv.w;
        }
    }
    #pragma unroll
    for (int p = 0; p < PPB; p++) {
        int pix = pix0 + p;
        if (pix < ES*ES) out[((long)n*ES*ES + pix)*128 + tid] = acc[p];
    }
}

// ---------------- correlation: 8-px tile, a in regs, shared b reads ----------------
// dyn smem: bsm[144][132]  (76,032 B)
__global__ __launch_bounds__(256) void corr_kernel(
        const float* __restrict__ fpm, const float* __restrict__ fpb,
        const float* __restrict__ fnm, float* __restrict__ corr)
{
    extern __shared__ float bsm[];       // [row 144][132]
    int blk = blockIdx.x;                // n*(65*9) + y*9 + xt
    int xt = blk % 9; int t = blk / 9;
    int y = t % ES;   int n = t / ES;
    int x0 = xt * 8;
    int tid = threadIdx.x;

    for (int i = tid; i < 144*32; i += 256) {
        int rc = i >> 5, c4 = i & 31;
        int dyi = rc >> 4, xc = rc & 15;
        int yy = y + dyi - 4, xx = x0 + xc - 4;
        float4 val = make_float4(0.f,0.f,0.f,0.f);
        if (yy >= 0 && yy < ES && xx >= 0 && xx < ES)
            val = ((const float4*)(fnm + ((long)n*ES*ES + yy*ES + xx)*128))[c4];
        *(float4*)(bsm + rc*132 + c4*4) = val;
    }
    __syncthreads();

    int w = tid >> 5;                    // warp = pixel index in tile
    int lane = tid & 31;
    int g = lane >> 2, q = lane & 3;     // 8 groups x 4 lanes
    int x = x0 + w;
    if (x >= ES) return;                 // warp-uniform (after the only sync)

    long apos = ((long)n*ES*ES + y*ES + x)*128;
    const float4* pm4 = (const float4*)(fpm + apos);
    const float4* pb4 = (const float4*)(fpb + apos);
    float4 am[8], ab[8];
    #pragma unroll
    for (int j = 0; j < 8; j++) {
        am[j] = pm4[j*4 + q];
        ab[j] = pb4[j*4 + q];
    }

    long obase = ((long)n*ES*ES + y*ES + x)*(long)S2;
    #pragma unroll
    for (int tb = 0; tb < 11; tb++) {
        int s = tb*8 + g;
        float dm = 0.f, db = 0.f;
        if (s < 81) {
            int dyi = s / 9, dxi = s % 9;
            const float* brow = bsm + (dyi*16 + w + dxi)*132;
            #pragma unroll
            for (int j = 0; j < 8; j++) {
                float4 bv = *(const float4*)(brow + (j*4 + q)*4);
                dm += am[j].x*bv.x + am[j].y*bv.y + am[j].z*bv.z + am[j].w*bv.w;
                db += ab[j].x*bv.x + ab[j].y*bv.y + ab[j].z*bv.z + ab[j].w*bv.w;
            }
        }
        dm += __shfl_xor_sync(0xffffffffu, dm, 1);
        dm += __shfl_xor_sync(0xffffffffu, dm, 2);
        db += __shfl_xor_sync(0xffffffffu, db, 1);
        db += __shfl_xor_sync(0xffffffffu, db, 2);
        if (q == 0 && s < 81) {
            corr[obase + s]      = dm * (1.0f/128.0f);
            corr[obase + 81 + s] = db * (1.0f/128.0f);
        }
    }
}

// ---------------- up2x (align_corners-style lerp, matches reference) ----------------
__global__ void up2x_kernel(const float* __restrict__ in, float* __restrict__ out,
                            int h, int ch, int nimg)
{
    long total = (long)nimg * (2*h) * (2*h) * ch;
    long idx = (long)blockIdx.x * blockDim.x + threadIdx.x;
    if (idx >= total) return;
    int c = (int)(idx % ch); long t = idx / ch;
    int h2 = 2*h;
    int xo = (int)(t % h2); t /= h2; int yo = (int)(t % h2); int n = (int)(t / h2);
    float fy = (float)(yo * (h-1)) / (float)(h2 - 1);
    float fx = (float)(xo * (h-1)) / (float)(h2 - 1);
    int iy0 = (int)floorf(fy), ix0 = (int)floorf(fx);
    float wy = fy - (float)iy0, wx = fx - (float)ix0;
    int iy1 = min(iy0+1, h-1), ix1 = min(ix0+1, h-1);
    const float* base = in + (long)n*h*h*ch;
    float v00 = base[(iy0*h + ix0)*ch + c];
    float v10 = base[(iy1*h + ix0)*ch + c];
    float v01 = base[(iy0*h + ix1)*ch + c];
    float v11 = base[(iy1*h + ix1)*ch + c];
    out[idx] = (v00*(1.f-wy) + v10*wy)*(1.f-wx) + (v01*(1.f-wy) + v11*wy)*wx;
}

// ---------------- conv1: 3x3, 162 -> 8, row-aligned warp/4px, 6-wide window reuse ----------------
// writes into 16-ch strided output at channel offset coff
__global__ __launch_bounds__(256) void conv1_kernel(
        const float* __restrict__ in, const float* __restrict__ w,
        const float* __restrict__ g, const float* __restrict__ bb,
        float* __restrict__ out, int coff)
{
    __shared__ float ws[9*8*S2];     // [kk][oc][ic]
    __shared__ float scale[ED], bsh[ED];
    int tid = threadIdx.x;
    for (int i = tid; i < 9*8*S2; i += 256) {
        int ic = i % S2; int t = i / S2; int oc = t & 7; int kk = t >> 3;
        ws[i] = w[(oc*S2 + ic)*9 + kk];
    }
    if (tid < ED) { scale[tid] = g[tid] * rsqrtf(1.0f + 1e-5f); bsh[tid] = bb[tid]; }
    __syncthreads();

    int lane = tid & 31;
    int wid = blockIdx.x*8 + (tid >> 5);   // global warp id
    int row = wid / 33;                    // n*U1 + y  (33 groups of 4 px per row)
    int xt  = wid % 33;
    int n = row / U1, y = row % U1;
    int x0 = xt * 4;
    long nbase = (long)n * (U1*U1);

    float acc[4][8];
    #pragma unroll
    for (int p = 0; p < 4; p++)
        #pragma unroll
        for (int o = 0; o < 8; o++) acc[p][o] = 0.f;

    #pragma unroll
    for (int ky = 0; ky < 3; ky++) {
        int iy = y + ky - 1;
        bool rowok = (iy >= 0 && iy < U1);
        const float* rbase = in + (nbase + (long)iy*U1)*(long)S2;
        #pragma unroll
        for (int jp = 0; jp < 3; jp++) {
            int ic2 = jp*32 + lane;
            bool act = ic2 < 81;           // 81 float2 per channel row
            int ic2c = act ? ic2 : 0;
            // 6-wide window: x0-1 .. x0+4 covers all 3 kx taps of 4 pixels
            float2 vv[6];
            #pragma unroll
            for (int j = 0; j < 6; j++) {
                int ix = x0 - 1 + j;
                bool ok = rowok && act && ix >= 0 && ix < U1;
                vv[j] = ok ? ((const float2*)(rbase + (long)ix*S2))[ic2c]
                           : make_float2(0.f, 0.f);
            }
            #pragma unroll
            for (int kx = 0; kx < 3; kx++) {
                const float* wpt = ws + (ky*3 + kx)*(8*S2);
                float2 wv[8];
                #pragma unroll
                for (int o = 0; o < 8; o++)
                    wv[o] = ((const float2*)(wpt + o*S2))[ic2c];
                #pragma unroll
                for (int p = 0; p < 4; p++)
                    #pragma unroll
                    for (int o = 0; o < 8; o++)
                        acc[p][o] += vv[kx+p].x*wv[o].x + vv[kx+p].y*wv[o].y;
            }
        }
    }
    // butterfly reduce across lanes (all lanes end with full sums)
    #pragma unroll
    for (int off = 16; off > 0; off >>= 1)
        #pragma unroll
        for (int p = 0; p < 4; p++)
            #pragma unroll
            for (int o = 0; o < 8; o++)
                acc[p][o] += __shfl_xor_sync(0xffffffffu, acc[p][o], off);

    #pragma unroll
    for (int p = 0; p < 4; p++) {
        if (lane == p && x0 + p < U1) {
            float* op = out + (nbase + (long)y*U1 + x0 + p)*ED2 + coff;
            #pragma unroll
            for (int o = 0; o < 8; o++)
                op[o] = fmaxf(acc[p][o]*scale[o] + bsh[o], 0.f);
        }
    }
}

// ---------------- conv2 fused: 3x3, (8->8)x2 branches, + bn/relu/1x1/scale ----------------
__global__ __launch_bounds__(256) void conv2_kernel(
        const float* __restrict__ in,
        const float* __restrict__ pw, const float* __restrict__ pg, const float* __restrict__ pb,
        const float* __restrict__ pow_, const float* __restrict__ pob, const float* __restrict__ pwt,
        const float* __restrict__ vw, const float* __restrict__ vg, const float* __restrict__ vb,
        const float* __restrict__ vow_, const float* __restrict__ vob, const float* __restrict__ vwt,
        float* __restrict__ phi, float* __restrict__ vort)
{
    __shared__ float ws[9*16*8];       // [kk][oc16][ic8]
    __shared__ float scale[ED2], bsh[ED2], owsh[ED2];
    int tid = threadIdx.x;
    for (int i = tid; i < 1152; i += 256) {
        int ic = i & 7, oc = (i >> 3) & 15, kk = i >> 7;
        ws[i] = (oc < 8) ? pw[(oc*8 + ic)*9 + kk] : vw[((oc-8)*8 + ic)*9 + kk];
    }
    if (tid < 8) {
        scale[tid]   = pg[tid] * rsqrtf(1.0f + 1e-5f);  bsh[tid]   = pb[tid];  owsh[tid]   = pow_[tid];
        scale[tid+8] = vg[tid] * rsqrtf(1.0f + 1e-5f);  bsh[tid+8] = vb[tid];  owsh[tid+8] = vow_[tid];
    }
    __syncthreads();

    int pix = blockIdx.x * 256 + tid;
    int x = pix % HW; int t = pix / HW; int y = t % HW; int n = t / HW;

    float acc[ED2];
    #pragma unroll
    for (int oc = 0; oc < ED2; oc++) acc[oc] = 0.f;

    #pragma unroll
    for (int ky = 0; ky < 3; ky++) {
        int iy = y + ky - 1; if (iy < 0 || iy >= HW) continue;
        #pragma unroll
        for (int kx = 0; kx < 3; kx++) {
            int ix = x + kx - 1; if (ix < 0 || ix >= HW) continue;
            const float4* ip4 = (const float4*)(in + ((long)n*HWHW + iy*HW + ix)*ED2);
            float4 s0 = ip4[0], s1 = ip4[1], s2 = ip4[2], s3 = ip4[3];
            const float* wp = ws + (ky*3 + kx)*128;
            #pragma unroll
            for (int oc = 0; oc < 8; oc++) {
                const float4* wq = (const float4*)(wp + oc*8);
                float4 w0 = wq[0], w1 = wq[1];
                acc[oc] += s0.x*w0.x + s0.y*w0.y + s0.z*w0.z + s0.w*w0.w
                         + s1.x*w1.x + s1.y*w1.y + s1.z*w1.z + s1.w*w1.w;
            }
            #pragma unroll
            for (int oc = 0; oc < 8; oc++) {
                const float4* wq = (const float4*)(wp + 64 + oc*8);
                float4 w0 = wq[0], w1 = wq[1];
                acc[8+oc] += s2.x*w0.x + s2.y*w0.y + s2.z*w0.z + s2.w*w0.w
                           + s3.x*w1.x + s3.y*w1.y + s3.z*w1.z + s3.w*w1.w;
            }
        }
    }
    float rp = 0.f, rv = 0.f;
    #pragma unroll
    for (int oc = 0; oc < 8; oc++)
        rp += fmaxf(acc[oc]*scale[oc] + bsh[oc], 0.f) * owsh[oc];
    #pragma unroll
    for (int oc = 0; oc < 8; oc++)
        rv += fmaxf(acc[8+oc]*scale[8+oc] + bsh[8+oc], 0.f) * owsh[8+oc];
    phi[pix]  = (rp + pob[0]) * pwt[0];
    vort[pix] = (rv + vob[0]) * vwt[0] * 260.0f;
}

// ---------------- velocity: fused helmholtz decode ----------------
__global__ void vel_kernel(const float* __restrict__ phi, const float* __restrict__ vort,
                           float* __restrict__ velx, float* __restrict__ vely)
{
    __shared__ float ku[36], kv[36];
    if (threadIdx.x < 36) { ku[threadIdx.x] = g_vortk[0][threadIdx.x]; kv[threadIdx.x] = g_vortk[1][threadIdx.x]; }
    __syncthreads();
    int idx = blockIdx.x * blockDim.x + threadIdx.x;
    if (idx >= NIMG*HTHT) return;
    int xo = idx % HT; int t = idx / HT; int yo = t % HT; int n = t / HT;
    const float* ph = phi  + (long)n*HWHW;
    const float* vo = vort + (long)n*HWHW;

    float vx = 0.5f*(ph[(yo+1)*HW + xo+2] - ph[(yo+1)*HW + xo]);
    float vy = 0.5f*(ph[(yo+2)*HW + xo+1] - ph[yo*HW + xo+1]);

    float p[7][7];
    #pragma unroll
    for (int r = 0; r < 7; r++) {
        int a = yo - 3 + r;
        #pragma unroll
        for (int c = 0; c < 7; c++) {
            int bcol = xo - 3 + c;
            p[r][c] = (a >= 0 && a <= 258 && bcol >= 0 && bcol <= 258) ? vo[a*HW + bcol] : 0.f;
        }
    }
    float su = 0.f, sv = 0.f;
    #pragma unroll
    for (int ky = 0; ky < 6; ky++)
        #pragma unroll
        for (int kx = 0; kx < 6; kx++) {
            su += ku[ky*6+kx] * (p[ky+1][kx+1] + p[ky+1][kx]);
            sv += kv[ky*6+kx] * (p[ky+1][kx+1] + p[ky][kx+1]);
        }
    velx[idx] = vx + 0.5f*su;
    vely[idx] = vy + 0.5f*sv;
}

// ---------------- bilinear warp (modes: 0=plain, 1=BFECC combine) ----------------
__global__ void warp_kernel(const float* __restrict__ src, const float* __restrict__ base,
                            const float* __restrict__ velx, const float* __restrict__ vely,
                            float sign, int mode, float* __restrict__ dst)
{
    int idx = blockIdx.x * blockDim.x + threadIdx.x;
    if (idx >= NIMG*HTHT) return;
    int x = idx % HT; int t = idx / HT; int y = t % HT; int n = t / HT;
    float px = (float)x - sign * velx[idx];
    float py = (float)y - sign * vely[idx];
    px = fminf(fmaxf(px, 0.f), (float)(HT-1));
    py = fminf(fmaxf(py, 0.f), (float)(HT-1));
    float fx = floorf(px), fy = floorf(py);
    float wx = px - fx, wy = py - fy;
    int x0 = (int)fx, y0 = (int)fy;
    int x1 = min(x0+1, HT-1), y1 = min(y0+1, HT-1);
    int o00 = y0*HT + x0, o01 = y0*HT + x1, o10 = y1*HT + x0, o11 = y1*HT + x1;
    int sp = y*HT + x;
    #pragma unroll
    for (int c = 0; c < ED; c++) {
        long pbase = (long)(n*ED + c) * HTHT;
        const float* pl = src + pbase;
        float v = (pl[o00]*(1.f-wx) + pl[o01]*wx)*(1.f-wy)
                + (pl[o10]*(1.f-wx) + pl[o11]*wx)*wy;
        float r = (mode == 1) ? (1.5f * base[pbase + sp] - 0.5f * v) : v;
        dst[pbase + sp] = r;
    }
}

// ---------------- per-pixel LayerNorm + MLP(64->64 gelu ->64) + residual ----------------
// 16 px/block, 4 px/thread-group
__global__ __launch_bounds__(256) void mlp_kernel(float* __restrict__ out,
                           const float* __restrict__ lng, const float* __restrict__ lnb,
                           const float* __restrict__ w1, const float* __restrict__ b1,
                           const float* __restrict__ w2, const float* __restrict__ b2)
{
    __shared__ float w1s[64*65], w2s[64*65];   // transposed, stride-65 (bank-safe)
    __shared__ float xn[16][64];
    __shared__ float hh[16][64];
    int tid = threadIdx.x;
    for (int i = tid; i < 4096; i += 256) {
        int r = i >> 6, cc = i & 63;           // r = out idx, cc = in idx
        w1s[cc*65 + r] = w1[i];
        w2s[cc*65 + r] = w2[i];
    }
    int c  = tid & 63;
    int g0 = (tid >> 6) * 4;                   // 4 pixels per thread, 16 per block
    float lg = lng[c], lb = lnb[c], b1v = b1[c], b2v = b2[c];

    int pix0 = blockIdx.x*16 + g0;             // grid exact: 4*HTHT/16

    float v[4]; float* pp[4];
    #pragma unroll
    for (int k = 0; k < 4; k++) {
        int pix = pix0 + k;
        int bi = pix / HTHT, sp = pix % HTHT;
        pp[k] = out + ((long)(bi*64 + c))*HTHT + sp;
        v[k] = *pp[k];
    }
    __syncthreads();
    #pragma unroll
    for (int k = 0; k < 4; k++) xn[g0+k][c] = v[k];
    __syncthreads();
    float xv[4];
    #pragma unroll
    for (int k = 0; k < 4; k++) {
        float mu = 0.f, m2 = 0.f;
        #pragma unroll 8
        for (int i = 0; i < 64; i++) { float tv = xn[g0+k][i]; mu += tv; m2 += tv*tv; }
        mu *= (1.0f/64.0f); m2 *= (1.0f/64.0f);
        float rs = rsqrtf(m2 - mu*mu + 1e-5f);
        xv[k] = (v[k] - mu)*rs*lg + lb;
    }
    __syncthreads();
    #pragma unroll
    for (int k = 0; k < 4; k++) xn[g0+k][c] = xv[k];
    __syncthreads();
    float h[4];
    #pragma unroll
    for (int k = 0; k < 4; k++) h[k] = b1v;
    #pragma unroll 8
    for (int i = 0; i < 64; i++) {
        float wv = w1s[i*65 + c];
        #pragma unroll
        for (int k = 0; k < 4; k++) h[k] += xn[g0+k][i]*wv;
    }
    #pragma unroll
    for (int k = 0; k < 4; k++) {
        h[k] = 0.5f*h[k]*(1.0f + erff(h[k]*0.70710678118654752f));
        hh[g0+k][c] = h[k];
    }
    __syncthreads();
    float yv[4];
    #pragma unroll
    for (int k = 0; k < 4; k++) yv[k] = b2v;
    #pragma unroll 8
    for (int j = 0; j < 64; j++) {
        float wv = w2s[j*65 + c];
        #pragma unroll
        for (int k = 0; k < 4; k++) yv[k] += hh[g0+k][j]*wv;
    }
    #pragma unroll
    for (int k = 0; k < 4; k++) *pp[k] = v[k] + yv[k];
}

// ---------------- launch ----------------
extern "C" void kernel_launch(void* const* d_in, const int* in_sizes, int n_in,
                              void* d_out, int out_size)
{
    const float* prev     = (const float*)d_in[0];
    const float* nxt      = (const float*)d_in[1];
    const float* texture  = (const float*)d_in[2];
    const float* mask     = (const float*)d_in[3];
    const float* boundary = (const float*)d_in[4];
    const float* enc_w    = (const float*)d_in[5];
    const float* enc_b    = (const float*)d_in[6];
    const float* phi_w1   = (const float*)d_in[7];
    const float* phi_g1   = (const float*)d_in[8];
    const float* phi_b1   = (const float*)d_in[9];
    const float* phi_w2   = (const float*)d_in[10];
    const float* phi_g2   = (const float*)d_in[11];
    const float* phi_b2   = (const float*)d_in[12];
    const float* phi_ow   = (const float*)d_in[13];
    const float* phi_ob   = (const float*)d_in[14];
    const float* vor_w1   = (const float*)d_in[15];
    const float* vor_g1   = (const float*)d_in[16];
    const float* vor_b1   = (const float*)d_in[17];
    const float* vor_w2   = (const float*)d_in[18];
    const float* vor_g2   = (const float*)d_in[19];
    const float* vor_b2   = (const float*)d_in[20];
    const float* vor_ow   = (const float*)d_in[21];
    const float* vor_ob   = (const float*)d_in[22];
    const float* phi_wt   = (const float*)d_in[23];
    const float* vor_wt   = (const float*)d_in[24];
    const float* ln_g     = (const float*)d_in[25];
    const float* ln_b     = (const float*)d_in[26];
    const float* fc1_w    = (const float*)d_in[27];
    const float* fc1_b    = (const float*)d_in[28];
    const float* fc2_w    = (const float*)d_in[29];
    const float* fc2_b    = (const float*)d_in[30];
    float* outp = (float*)d_out;

    float *fnm, *fpm, *fpb, *corr, *upcorr, *t1, *upt1, *phi, *vort, *velx, *vely, *wa, *wb, *wt;
    cudaGetSymbolAddress((void**)&fnm,    g_fnm);
    cudaGetSymbolAddress((void**)&fpm,    g_fpm);
    cudaGetSymbolAddress((void**)&fpb,    g_fpb);
    cudaGetSymbolAddress((void**)&corr,   g_corr);
    cudaGetSymbolAddress((void**)&upcorr, g_upcorr);
    cudaGetSymbolAddress((void**)&t1,     g_t1);
    cudaGetSymbolAddress((void**)&upt1,   g_upt1);
    cudaGetSymbolAddress((void**)&phi,    g_phi);
    cudaGetSymbolAddress((void**)&vort,   g_vort);
    cudaGetSymbolAddress((void**)&velx,   g_velx);
    cudaGetSymbolAddress((void**)&vely,   g_vely);
    cudaGetSymbolAddress((void**)&wa,     g_wa);
    cudaGetSymbolAddress((void**)&wb,     g_wb);
    cudaGetSymbolAddress((void**)&wt,     g_wt);

    const int corr_smem = 144*132*4;     // 76,032 B
    cudaFuncSetAttribute(corr_kernel, cudaFuncAttributeMaxDynamicSharedMemorySize, corr_smem);

    init_kernel<<<32, 512>>>(enc_w);

    dim3 egrid((ES*ES + 31)/32, NIMG);
    enc_kernel<<<egrid, 128>>>(nxt,  mask,     wt, enc_b, fnm);
    enc_kernel<<<egrid, 128>>>(prev, mask,     wt, enc_b, fpm);
    enc_kernel<<<egrid, 128>>>(prev, boundary, wt, enc_b, fpb);

    corr_kernel<<<NIMG*ES*9, 256, corr_smem>>>(fpm, fpb, fnm, corr);

    {
        long total = (long)NIMG*U1*U1*S2;
        up2x_kernel<<<(unsigned)((total + 255)/256), 256>>>(corr, upcorr, ES, S2, NIMG);
    }

    // decoder: conv1 x2 (into shared 16-ch buffer), one 16-ch up2x, fused conv2
    // row-aligned: 33 groups of 4 px per row; warps = NIMG*U1*33 (exact /8)
    int c1blocks = (NIMG*U1*33) / 8;
    conv1_kernel<<<c1blocks, 256>>>(upcorr, phi_w1, phi_g1, phi_b1, t1, 0);
    conv1_kernel<<<c1blocks, 256>>>(upcorr, vor_w1, vor_g1, vor_b1, t1, 8);
    {
        long total = (long)NIMG*HWHW*ED2;
        up2x_kernel<<<(unsigned)((total + 255)/256), 256>>>(t1, upt1, U1, ED2, NIMG);
    }
    conv2_kernel<<<(NIMG*HWHW)/256, 256>>>(upt1,
        phi_w2, phi_g2, phi_b2, phi_ow, phi_ob, phi_wt,
        vor_w2, vor_g2, vor_b2, vor_ow, vor_ob, vor_wt,
        phi, vort);

    int vblocks = (NIMG*HTHT + 255)/256;
    vel_kernel<<<vblocks, 256>>>(phi, vort, velx, vely);

    // BFECC: f1 = warp(tex,+1); f2 = 1.5*tex - 0.5*warp(f1,-1); pred = warp(f2,+1)
    warp_kernel<<<vblocks, 256>>>(texture, nullptr,  velx, vely,  1.0f, 0, wa);
    warp_kernel<<<vblocks, 256>>>(wa,      texture,  velx, vely, -1.0f, 1, wb);
    warp_kernel<<<vblocks, 256>>>(wb,      nullptr,  velx, vely,  1.0f, 0, outp);

    // 16 px per block, 4 px per thread: grid = 4*HTHT/16 (exact: 266256/16 = 16641)
    mlp_kernel<<<(4*HTHT)/16, 256>>>(outp, ln_g, ln_b, fc1_w, fc1_b, fc2_w, fc2_b);
}